// round 1
// baseline (speedup 1.0000x reference)
#include <cuda_runtime.h>
#include <math.h>

// Problem constants
#define Bdim 8
#define Hdim 252
#define Wdim 192
#define Cdim 64
#define Edim 192
#define HHn  84
#define WWn  64
#define NB   (Bdim*HHn*WWn)        // 43008 3x3 blocks
#define NPIX (Bdim*Hdim*Wdim)      // 387072 pixels
#define NATT 486                   // K^4 * HEADS = 81*6
#define NHEADS 6
#define KDim 32
#define SCALE_F 0.17677669529663687f  // 32^-0.5

// Scratch (device globals; no runtime allocation allowed)
__device__ float g_attn[(size_t)NB * NATT];      // softmaxed attention  (~84 MB)
__device__ float g_mid[(size_t)NPIX * Edim];     // pre-projection output (~297 MB)

// ---------------------------------------------------------------------------
// Kernel 1: pooled mean + attn GEMM (+bias,*scale) + softmax, fused.
// CTA handles 16 consecutive blocks. 512 threads.
// ---------------------------------------------------------------------------
__global__ __launch_bounds__(512) void attn_kernel(
    const float* __restrict__ x,
    const float* __restrict__ attn_w,
    const float* __restrict__ attn_b)
{
    __shared__ float pooled_s[16][64];
    __shared__ float attn_s[16][NATT + 2];

    const int blk0 = blockIdx.x * 16;
    const int tid  = threadIdx.x;

    // ---- pooled[ml][c] = mean over 3x3 pixels ----
    for (int idx = tid; idx < 16 * 64; idx += 512) {
        int ml = idx >> 6, c = idx & 63;
        int blk = blk0 + ml;
        int b   = blk / (HHn * WWn);
        int rem = blk % (HHn * WWn);
        int i   = rem / WWn;
        int j   = rem % WWn;
        const float* xp = x + ((size_t)((size_t)b * Hdim + 3 * i) * Wdim + 3 * j) * Cdim + c;
        float s = 0.f;
        #pragma unroll
        for (int r = 0; r < 3; r++)
            #pragma unroll
            for (int ss = 0; ss < 3; ss++)
                s += xp[((size_t)r * Wdim + ss) * Cdim];
        pooled_s[ml][c] = s * (1.f / 9.f);
    }
    __syncthreads();

    // ---- GEMM: [16 x 64] @ [64 x 486], thread = one output column ----
    if (tid < NATT) {
        float acc[16];
        #pragma unroll
        for (int m = 0; m < 16; m++) acc[m] = 0.f;
        #pragma unroll 4
        for (int c = 0; c < 64; c++) {
            float w = attn_w[c * NATT + tid];
            #pragma unroll
            for (int m = 0; m < 16; m++) acc[m] += pooled_s[m][c] * w;
        }
        float bb = attn_b[tid];
        #pragma unroll
        for (int m = 0; m < 16; m++) attn_s[m][tid] = (acc[m] + bb) * SCALE_F;
    }
    __syncthreads();

    // ---- softmax over groups of 9 (54 groups per row) ----
    for (int t = tid; t < 16 * 54; t += 512) {
        int m = t / 54, g = t % 54;
        float* p = &attn_s[m][g * 9];
        float mx = p[0];
        #pragma unroll
        for (int q = 1; q < 9; q++) mx = fmaxf(mx, p[q]);
        float e[9];
        float s = 0.f;
        #pragma unroll
        for (int q = 0; q < 9; q++) { e[q] = __expf(p[q] - mx); s += e[q]; }
        float inv = 1.f / s;
        float* outp = &g_attn[(size_t)(blk0 + m) * NATT + g * 9];
        #pragma unroll
        for (int q = 0; q < 9; q++) outp[q] = e[q] * inv;
    }
}

// ---------------------------------------------------------------------------
// Kernel 2: fused v = x9@v_w and o = attn@v per 3x3 block -> g_mid.
// One CTA per block, 192 threads; thread e keeps v[9] and o[9] in registers.
// v_w streamed straight from global (each element used once per CTA, reused
// 9x in registers) -> no big smem tile, high occupancy.
// ---------------------------------------------------------------------------
__global__ __launch_bounds__(192) void ov_kernel(
    const float* __restrict__ x,
    const float* __restrict__ v_w)
{
    __shared__ float sx[9 * 64];     // x block, [p][c]
    __shared__ float sa[NATT];       // softmaxed attention for this block

    const int tid = threadIdx.x;
    const int blk = blockIdx.x;
    const int b   = blk / (HHn * WWn);
    const int rem = blk % (HHn * WWn);
    const int i   = rem / WWn;
    const int j   = rem % WWn;

    const float* xbase = x + ((size_t)((size_t)b * Hdim + 3 * i) * Wdim + 3 * j) * Cdim;
    for (int idx = tid; idx < 576; idx += 192) {
        int p = idx >> 6, c = idx & 63;
        int r = p / 3, s = p % 3;
        sx[idx] = xbase[((size_t)r * Wdim + s) * Cdim + c];
    }
    const float* ga = &g_attn[(size_t)blk * NATT];
    for (int t = tid; t < NATT; t += 192) sa[t] = ga[t];
    __syncthreads();

    const int e = tid;
    float vacc[9];
    #pragma unroll
    for (int p = 0; p < 9; p++) vacc[p] = 0.f;

    #pragma unroll
    for (int c4 = 0; c4 < 16; c4++) {
        // 4 weights for channels 4*c4 .. 4*c4+3, coalesced across lanes
        float w0 = __ldg(&v_w[(size_t)(4 * c4 + 0) * Edim + e]);
        float w1 = __ldg(&v_w[(size_t)(4 * c4 + 1) * Edim + e]);
        float w2 = __ldg(&v_w[(size_t)(4 * c4 + 2) * Edim + e]);
        float w3 = __ldg(&v_w[(size_t)(4 * c4 + 3) * Edim + e]);
        #pragma unroll
        for (int p = 0; p < 9; p++) {
            float4 xv = *(const float4*)&sx[p * 64 + c4 * 4];
            vacc[p] += xv.x * w0;
            vacc[p] += xv.y * w1;
            vacc[p] += xv.z * w2;
            vacc[p] += xv.w * w3;
        }
    }

    // o[p] = sum_q attn[h][p][q] * v[q]
    const int h = e >> 5;
    const float* ah = &sa[h * 81];
    float o[9];
    #pragma unroll
    for (int p = 0; p < 9; p++) {
        float acc = 0.f;
        #pragma unroll
        for (int q = 0; q < 9; q++) acc += ah[p * 9 + q] * vacc[q];
        o[p] = acc;
    }

    float* mbase = &g_mid[((size_t)((size_t)b * Hdim + 3 * i) * Wdim + 3 * j) * Edim + e];
    #pragma unroll
    for (int p = 0; p < 9; p++) {
        int r = p / 3, s = p % 3;
        mbase[((size_t)r * Wdim + s) * Edim] = o[p];
    }
}

// ---------------------------------------------------------------------------
// Kernel 3: projection GEMM  out = g_mid[NPIX,192] @ out_w[192,192] + out_b.
// CTA tile 64(M) x 192(N), 256 threads, 4x12 register tile per thread.
// ---------------------------------------------------------------------------
__global__ __launch_bounds__(256) void proj_kernel(
    const float* __restrict__ out_w,
    const float* __restrict__ out_b,
    float* __restrict__ outp)
{
    __shared__ float As[32 * 68];    // A chunk, transposed [k][m], padded
    __shared__ float Ws[32 * 192];   // W chunk [k][n]

    const int tid = threadIdx.x;
    const int m0  = blockIdx.x * 64;
    const int mt  = (tid >> 4) * 4;        // 0..60 step 4
    const int n0  = (tid & 15) * 12;       // 0..180 step 12

    float acc[4][12];
    #pragma unroll
    for (int a = 0; a < 4; a++)
        #pragma unroll
        for (int c = 0; c < 12; c++) acc[a][c] = 0.f;

    for (int kc = 0; kc < 192; kc += 32) {
        // load A [64 x 32] -> transposed smem
        #pragma unroll
        for (int it = 0; it < 2; it++) {
            int fidx = it * 256 + tid;           // 0..511
            int m = fidx >> 3, kq = fidx & 7;
            float4 v = *(const float4*)&g_mid[(size_t)(m0 + m) * 192 + kc + kq * 4];
            As[(kq * 4 + 0) * 68 + m] = v.x;
            As[(kq * 4 + 1) * 68 + m] = v.y;
            As[(kq * 4 + 2) * 68 + m] = v.z;
            As[(kq * 4 + 3) * 68 + m] = v.w;
        }
        // load W [32 x 192]
        #pragma unroll
        for (int it = 0; it < 6; it++) {
            int fidx = it * 256 + tid;           // 0..1535
            int k = fidx / 48, nq = fidx % 48;
            *(float4*)&Ws[k * 192 + nq * 4] =
                *(const float4*)&out_w[(size_t)(kc + k) * 192 + nq * 4];
        }
        __syncthreads();

        #pragma unroll
        for (int k = 0; k < 32; k++) {
            float4 a4 = *(const float4*)&As[k * 68 + mt];
            float av[4] = {a4.x, a4.y, a4.z, a4.w};
            float bv[12];
            *(float4*)&bv[0] = *(const float4*)&Ws[k * 192 + n0];
            *(float4*)&bv[4] = *(const float4*)&Ws[k * 192 + n0 + 4];
            *(float4*)&bv[8] = *(const float4*)&Ws[k * 192 + n0 + 8];
            #pragma unroll
            for (int mi = 0; mi < 4; mi++)
                #pragma unroll
                for (int ni = 0; ni < 12; ni++)
                    acc[mi][ni] += av[mi] * bv[ni];
        }
        __syncthreads();
    }

    float bias[12];
    *(float4*)&bias[0] = *(const float4*)&out_b[n0];
    *(float4*)&bias[4] = *(const float4*)&out_b[n0 + 4];
    *(float4*)&bias[8] = *(const float4*)&out_b[n0 + 8];

    #pragma unroll
    for (int mi = 0; mi < 4; mi++) {
        float* op = &outp[(size_t)(m0 + mt + mi) * 192 + n0];
        #pragma unroll
        for (int nq = 0; nq < 3; nq++) {
            float4 v;
            v.x = acc[mi][nq * 4 + 0] + bias[nq * 4 + 0];
            v.y = acc[mi][nq * 4 + 1] + bias[nq * 4 + 1];
            v.z = acc[mi][nq * 4 + 2] + bias[nq * 4 + 2];
            v.w = acc[mi][nq * 4 + 3] + bias[nq * 4 + 3];
            *(float4*)&op[nq * 4] = v;
        }
    }
}

// ---------------------------------------------------------------------------
extern "C" void kernel_launch(void* const* d_in, const int* in_sizes, int n_in,
                              void* d_out, int out_size)
{
    const float* x      = (const float*)d_in[0];
    const float* v_w    = (const float*)d_in[1];
    const float* attn_w = (const float*)d_in[2];
    const float* attn_b = (const float*)d_in[3];
    const float* out_w  = (const float*)d_in[4];
    const float* out_b  = (const float*)d_in[5];
    float* outp = (float*)d_out;

    attn_kernel<<<NB / 16, 512>>>(x, attn_w, attn_b);
    ov_kernel<<<NB, 192>>>(x, v_w);
    proj_kernel<<<NPIX / 64, 256>>>(out_w, out_b, outp);
}

// round 4
// speedup vs baseline: 1.5014x; 1.5014x over previous
#include <cuda_runtime.h>
#include <cuda_bf16.h>
#include <math.h>
#include <stdint.h>

// Problem constants
#define Bdim 8
#define Hdim 252
#define Wdim 192
#define Cdim 64
#define Edim 192
#define HHn  84
#define WWn  64
#define NB   (Bdim*HHn*WWn)        // 43008 3x3 blocks
#define NPIX (Bdim*Hdim*Wdim)      // 387072 pixels
#define NATT 486                   // K^4 * HEADS = 81*6
#define SCALE_F 0.17677669529663687f  // 32^-0.5

// Scratch (device globals; no runtime allocation allowed)
__device__ float g_attn[(size_t)NB * NATT];                    // softmaxed attention (~84 MB)
__device__ __nv_bfloat16 g_mid_hi[(size_t)NPIX * Edim];        // mid, bf16 hi (~149 MB)
__device__ __nv_bfloat16 g_mid_lo[(size_t)NPIX * Edim];        // mid, bf16 lo (~149 MB)
__device__ __nv_bfloat16 g_wt_hi[Edim * Edim];                 // out_w^T hi, [n][k]
__device__ __nv_bfloat16 g_wt_lo[Edim * Edim];                 // out_w^T lo, [n][k]

// ---------------------------------------------------------------------------
// f32x2 helpers (packed FFMA2; plain sm_100-family fp ops, no 'a' suffix)
// ---------------------------------------------------------------------------
__device__ __forceinline__ unsigned long long fma2(unsigned long long a,
                                                   unsigned long long b,
                                                   unsigned long long c) {
    unsigned long long d;
    asm("fma.rn.f32x2 %0, %1, %2, %3;" : "=l"(d) : "l"(a), "l"(b), "l"(c));
    return d;
}
__device__ __forceinline__ unsigned long long splat2(float v) {
    unsigned long long d;
    asm("mov.b64 %0, {%1, %1};" : "=l"(d) : "r"(__float_as_uint(v)));
    return d;
}
__device__ __forceinline__ float2 unpk2(unsigned long long v) {
    float2 r;
    asm("mov.b64 {%0, %1}, %2;" : "=f"(r.x), "=f"(r.y) : "l"(v));
    return r;
}

// ---------------------------------------------------------------------------
// Kernel 0: split out_w into transposed bf16 hi/lo:  wt[n][k] = out_w[k][n]
// ---------------------------------------------------------------------------
__global__ __launch_bounds__(256) void prep_kernel(const float* __restrict__ out_w)
{
    int idx = blockIdx.x * 256 + threadIdx.x;
    if (idx < Edim * Edim) {
        int n = idx / Edim, k = idx % Edim;
        float w = out_w[(size_t)k * Edim + n];
        __nv_bfloat16 h = __float2bfloat16(w);
        g_wt_hi[idx] = h;
        g_wt_lo[idx] = __float2bfloat16(w - __bfloat162float(h));
    }
}

// ---------------------------------------------------------------------------
// Kernel 1: pooled mean + attn GEMM (+bias,*scale) + softmax.  f32x2 over m.
// ---------------------------------------------------------------------------
__global__ __launch_bounds__(512) void attn_kernel(
    const float* __restrict__ x,
    const float* __restrict__ attn_w,
    const float* __restrict__ attn_b)
{
    __shared__ float pooled_t[64][18];          // [c][m], padded
    __shared__ float attn_s[16][NATT + 2];

    const int blk0 = blockIdx.x * 16;
    const int tid  = threadIdx.x;

    // pooled, stored transposed [c][m]
    for (int idx = tid; idx < 16 * 64; idx += 512) {
        int ml = idx >> 6, c = idx & 63;
        int blk = blk0 + ml;
        int b   = blk / (HHn * WWn);
        int rem = blk % (HHn * WWn);
        int i   = rem / WWn;
        int j   = rem % WWn;
        const float* xp = x + ((size_t)((size_t)b * Hdim + 3 * i) * Wdim + 3 * j) * Cdim + c;
        float s = 0.f;
        #pragma unroll
        for (int r = 0; r < 3; r++)
            #pragma unroll
            for (int ss = 0; ss < 3; ss++)
                s += xp[((size_t)r * Wdim + ss) * Cdim];
        pooled_t[c][ml] = s * (1.f / 9.f);
    }
    __syncthreads();

    // GEMM: [16 x 64] @ [64 x 486], thread = one column, f32x2 over m-pairs
    if (tid < NATT) {
        unsigned long long acc2[8];
        #pragma unroll
        for (int mp = 0; mp < 8; mp++) acc2[mp] = 0ull;
        #pragma unroll 4
        for (int c = 0; c < 64; c++) {
            unsigned long long wp = splat2(attn_w[c * NATT + tid]);
            #pragma unroll
            for (int mp = 0; mp < 8; mp++) {
                unsigned long long pp =
                    *(const unsigned long long*)&pooled_t[c][2 * mp];
                acc2[mp] = fma2(pp, wp, acc2[mp]);
            }
        }
        float bb = attn_b[tid];
        #pragma unroll
        for (int mp = 0; mp < 8; mp++) {
            float2 f = unpk2(acc2[mp]);
            attn_s[2 * mp + 0][tid] = (f.x + bb) * SCALE_F;
            attn_s[2 * mp + 1][tid] = (f.y + bb) * SCALE_F;
        }
    }
    __syncthreads();

    // softmax over groups of 9
    for (int t = tid; t < 16 * 54; t += 512) {
        int m = t / 54, g = t % 54;
        float* p = &attn_s[m][g * 9];
        float mx = p[0];
        #pragma unroll
        for (int q = 1; q < 9; q++) mx = fmaxf(mx, p[q]);
        float e[9];
        float s = 0.f;
        #pragma unroll
        for (int q = 0; q < 9; q++) { e[q] = __expf(p[q] - mx); s += e[q]; }
        float inv = 1.f / s;
        float* outp = &g_attn[(size_t)(blk0 + m) * NATT + g * 9];
        #pragma unroll
        for (int q = 0; q < 9; q++) outp[q] = e[q] * inv;
    }
}

// ---------------------------------------------------------------------------
// Kernel 2: fused v = x9@v_w and o = attn@v, f32x2 over embed-pairs.
// Writes mid as bf16 hi/lo.
// ---------------------------------------------------------------------------
__global__ __launch_bounds__(192) void ov_kernel(
    const float* __restrict__ x,
    const float* __restrict__ v_w)
{
    __shared__ float sxx[2][9 * 128];      // splatted x: [(p*64+c)*2 + {0,1}]
    __shared__ float saa[2][NATT * 2];     // splatted attn

    const int tid  = threadIdx.x;
    const int lb   = tid / 96;
    const int ep   = tid % 96;
    const int e0   = ep * 2;
    const int blk0 = blockIdx.x * 2;

    // load + splat x for both blocks (288 float4 total)
    for (int idx = tid; idx < 288; idx += 192) {
        int l = idx / 144, t = idx % 144;
        int blk = blk0 + l;
        int b   = blk / (HHn * WWn);
        int rem = blk % (HHn * WWn);
        int i   = rem / WWn;
        int j   = rem % WWn;
        int r = t / 48, u = t % 48;
        float4 v = *(const float4*)&x[((size_t)((size_t)b * Hdim + 3 * i + r) * Wdim + 3 * j) * Cdim + u * 4];
        int base = (r * 192 + u * 4) * 2;
        *(float2*)&sxx[l][base + 0] = make_float2(v.x, v.x);
        *(float2*)&sxx[l][base + 2] = make_float2(v.y, v.y);
        *(float2*)&sxx[l][base + 4] = make_float2(v.z, v.z);
        *(float2*)&sxx[l][base + 6] = make_float2(v.w, v.w);
    }
    // load + splat attention
    for (int idx = tid; idx < 2 * NATT; idx += 192) {
        int l = idx / NATT, t = idx % NATT;
        float a = g_attn[(size_t)(blk0 + l) * NATT + t];
        *(float2*)&saa[l][t * 2] = make_float2(a, a);
    }
    __syncthreads();

    unsigned long long vacc[9];
    #pragma unroll
    for (int p = 0; p < 9; p++) vacc[p] = 0ull;

    #pragma unroll 2
    for (int c4 = 0; c4 < 16; c4++) {
        const float* wb = &v_w[(size_t)(4 * c4) * Edim + e0];
        unsigned long long w0 = *(const unsigned long long*)(wb + 0 * Edim);
        unsigned long long w1 = *(const unsigned long long*)(wb + 1 * Edim);
        unsigned long long w2 = *(const unsigned long long*)(wb + 2 * Edim);
        unsigned long long w3 = *(const unsigned long long*)(wb + 3 * Edim);
        #pragma unroll
        for (int p = 0; p < 9; p++) {
            const unsigned long long* xp =
                (const unsigned long long*)&sxx[lb][(p * 64 + 4 * c4) * 2];
            unsigned long long a = vacc[p];
            a = fma2(xp[0], w0, a);
            a = fma2(xp[1], w1, a);
            a = fma2(xp[2], w2, a);
            a = fma2(xp[3], w3, a);
            vacc[p] = a;
        }
    }

    const int h = ep >> 4;
    const int blk = blk0 + lb;
    const int b   = blk / (HHn * WWn);
    const int rem = blk % (HHn * WWn);
    const int i   = rem / WWn;
    const int j   = rem % WWn;

    #pragma unroll
    for (int p = 0; p < 9; p++) {
        const unsigned long long* ap =
            (const unsigned long long*)&saa[lb][(h * 81 + p * 9) * 2];
        unsigned long long o2 = 0ull;
        #pragma unroll
        for (int q = 0; q < 9; q++) o2 = fma2(ap[q], vacc[q], o2);
        float2 f = unpk2(o2);

        int r = p / 3, s = p % 3;
        size_t pix = (size_t)((size_t)b * Hdim + 3 * i + r) * Wdim + 3 * j + s;
        __nv_bfloat16 hx = __float2bfloat16(f.x);
        __nv_bfloat16 hy = __float2bfloat16(f.y);
        __nv_bfloat16 lx = __float2bfloat16(f.x - __bfloat162float(hx));
        __nv_bfloat16 ly = __float2bfloat16(f.y - __bfloat162float(hy));
        *(__nv_bfloat162*)&g_mid_hi[pix * Edim + e0] = __halves2bfloat162(hx, hy);
        *(__nv_bfloat162*)&g_mid_lo[pix * Edim + e0] = __halves2bfloat162(lx, ly);
    }
}

// ---------------------------------------------------------------------------
// Kernel 3: projection via warp-level HMMA (mma.sync m16n8k16 bf16, sm_80+).
// out[m][n] = hi@Whi + hi@Wlo + lo@Whi  (single fp32 accumulator)
// CTA tile M=128, N=192; K-chunks of 64 in smem (144B padded rows).
// 256 threads = 8 warps; warp tile 32(M) x 96(N).
// ---------------------------------------------------------------------------
#define SROW 144                               // padded smem row bytes (64 bf16 + 16B)
#define OFF_AH 0
#define OFF_AL (128 * SROW)                    // 18432
#define OFF_BH (2 * 128 * SROW)                // 36864
#define OFF_BL (OFF_BH + 192 * SROW)           // 64512
#define PSM_TOTAL (OFF_BL + 192 * SROW)        // 92160 bytes

__device__ __forceinline__ void mma16816(float* c, const uint32_t* a,
                                         uint32_t b0, uint32_t b1) {
    asm("mma.sync.aligned.m16n8k16.row.col.f32.bf16.bf16.f32 "
        "{%0,%1,%2,%3}, {%4,%5,%6,%7}, {%8,%9}, {%0,%1,%2,%3};"
        : "+f"(c[0]), "+f"(c[1]), "+f"(c[2]), "+f"(c[3])
        : "r"(a[0]), "r"(a[1]), "r"(a[2]), "r"(a[3]), "r"(b0), "r"(b1));
}

__global__ __launch_bounds__(256) void proj_hmma_kernel(
    const float* __restrict__ out_b,
    float* __restrict__ outp)
{
    extern __shared__ char smem[];

    const int tid    = threadIdx.x;
    const int warp   = tid >> 5;
    const int lane   = tid & 31;
    const int g      = lane >> 2;          // 0..7
    const int t      = lane & 3;           // 0..3
    const int warp_m = warp & 3;           // 0..3  (rows warp_m*32)
    const int warp_n = warp >> 2;          // 0..1  (cols warp_n*96)

    const size_t m0 = (size_t)blockIdx.x * 128;
    const char* Ah = (const char*)(g_mid_hi + m0 * Edim);
    const char* Al = (const char*)(g_mid_lo + m0 * Edim);
    const char* Bh = (const char*)g_wt_hi;
    const char* Bl = (const char*)g_wt_lo;

    float acc[2][12][4];
    #pragma unroll
    for (int mt = 0; mt < 2; mt++)
        #pragma unroll
        for (int nt = 0; nt < 12; nt++)
            #pragma unroll
            for (int q = 0; q < 4; q++) acc[mt][nt][q] = 0.f;

    for (int ch = 0; ch < 3; ch++) {
        const int kb = ch * 128;           // byte offset of K-chunk in 384B row

        // fill A (128 rows) hi+lo
        #pragma unroll
        for (int it = 0; it < 4; it++) {
            int idx = it * 256 + tid;      // 0..1023
            int row = idx >> 3, q = idx & 7;
            size_t gsrc = (size_t)row * 384 + kb + q * 16;
            int    sdst = row * SROW + q * 16;
            *(uint4*)(smem + OFF_AH + sdst) = *(const uint4*)(Ah + gsrc);
            *(uint4*)(smem + OFF_AL + sdst) = *(const uint4*)(Al + gsrc);
        }
        // fill B (192 rows) hi+lo
        #pragma unroll
        for (int it = 0; it < 6; it++) {
            int idx = it * 256 + tid;      // 0..1535
            int row = idx >> 3, q = idx & 7;
            size_t gsrc = (size_t)row * 384 + kb + q * 16;
            int    sdst = row * SROW + q * 16;
            *(uint4*)(smem + OFF_BH + sdst) = *(const uint4*)(Bh + gsrc);
            *(uint4*)(smem + OFF_BL + sdst) = *(const uint4*)(Bl + gsrc);
        }
        __syncthreads();

        #pragma unroll
        for (int ks = 0; ks < 4; ks++) {
            const int ko = ks * 32 + t * 4;        // byte offset of this thread's k pair
            // A fragments for both m-tiles, hi and lo
            uint32_t ah[2][4], al[2][4];
            #pragma unroll
            for (int mt = 0; mt < 2; mt++) {
                int r0 = (warp_m * 32 + mt * 16 + g) * SROW;
                int r1 = r0 + 8 * SROW;
                ah[mt][0] = *(const uint32_t*)(smem + OFF_AH + r0 + ko);
                ah[mt][1] = *(const uint32_t*)(smem + OFF_AH + r1 + ko);
                ah[mt][2] = *(const uint32_t*)(smem + OFF_AH + r0 + ko + 16);
                ah[mt][3] = *(const uint32_t*)(smem + OFF_AH + r1 + ko + 16);
                al[mt][0] = *(const uint32_t*)(smem + OFF_AL + r0 + ko);
                al[mt][1] = *(const uint32_t*)(smem + OFF_AL + r1 + ko);
                al[mt][2] = *(const uint32_t*)(smem + OFF_AL + r0 + ko + 16);
                al[mt][3] = *(const uint32_t*)(smem + OFF_AL + r1 + ko + 16);
            }
            #pragma unroll
            for (int nt = 0; nt < 12; nt++) {
                int nr = (warp_n * 96 + nt * 8 + g) * SROW;
                uint32_t bh0 = *(const uint32_t*)(smem + OFF_BH + nr + ko);
                uint32_t bh1 = *(const uint32_t*)(smem + OFF_BH + nr + ko + 16);
                uint32_t bl0 = *(const uint32_t*)(smem + OFF_BL + nr + ko);
                uint32_t bl1 = *(const uint32_t*)(smem + OFF_BL + nr + ko + 16);
                #pragma unroll
                for (int mt = 0; mt < 2; mt++) {
                    mma16816(acc[mt][nt], ah[mt], bh0, bh1);
                    mma16816(acc[mt][nt], ah[mt], bl0, bl1);
                    mma16816(acc[mt][nt], al[mt], bh0, bh1);
                }
            }
        }
        __syncthreads();
    }

    // epilogue: c0,c1 -> (row g, cols 2t,2t+1); c2,c3 -> row g+8
    #pragma unroll
    for (int nt = 0; nt < 12; nt++) {
        int col = warp_n * 96 + nt * 8 + 2 * t;
        float2 bb = *(const float2*)&out_b[col];
        #pragma unroll
        for (int mt = 0; mt < 2; mt++) {
            size_t row = m0 + warp_m * 32 + mt * 16 + g;
            float2 v0 = make_float2(acc[mt][nt][0] + bb.x, acc[mt][nt][1] + bb.y);
            float2 v1 = make_float2(acc[mt][nt][2] + bb.x, acc[mt][nt][3] + bb.y);
            *(float2*)&outp[row * Edim + col]       = v0;
            *(float2*)&outp[(row + 8) * Edim + col] = v1;
        }
    }
}

// ---------------------------------------------------------------------------
extern "C" void kernel_launch(void* const* d_in, const int* in_sizes, int n_in,
                              void* d_out, int out_size)
{
    const float* x      = (const float*)d_in[0];
    const float* v_w    = (const float*)d_in[1];
    const float* attn_w = (const float*)d_in[2];
    const float* attn_b = (const float*)d_in[3];
    const float* out_w  = (const float*)d_in[4];
    const float* out_b  = (const float*)d_in[5];
    float* outp = (float*)d_out;

    cudaFuncSetAttribute(proj_hmma_kernel,
                         cudaFuncAttributeMaxDynamicSharedMemorySize, PSM_TOTAL);

    prep_kernel<<<(Edim * Edim + 255) / 256, 256>>>(out_w);
    attn_kernel<<<NB / 16, 512>>>(x, attn_w, attn_b);
    ov_kernel<<<NB / 2, 192>>>(x, v_w);
    proj_hmma_kernel<<<NPIX / 128, 256, PSM_TOTAL>>>(out_b, outp);
}

// round 8
// speedup vs baseline: 1.5077x; 1.0042x over previous
#include <cuda_runtime.h>
#include <cuda_bf16.h>
#include <math.h>
#include <stdint.h>

// Problem constants
#define Bdim 8
#define Hdim 252
#define Wdim 192
#define Cdim 64
#define Edim 192
#define HHn  84
#define WWn  64
#define NB   (Bdim*HHn*WWn)        // 43008 3x3 blocks
#define NPIX (Bdim*Hdim*Wdim)      // 387072 pixels
#define NATT 486                   // K^4 * HEADS = 81*6
#define SCALE_F 0.17677669529663687f  // 32^-0.5

// Scratch (device globals; no runtime allocation allowed)
__device__ float g_attn[(size_t)NB * NATT];                    // softmaxed attention (~84 MB)
__device__ __nv_bfloat16 g_mid_hi[(size_t)NPIX * Edim];        // mid, bf16 hi (~149 MB)
__device__ __nv_bfloat16 g_mid_lo[(size_t)NPIX * Edim];        // mid, bf16 lo (~149 MB)
__device__ __nv_bfloat16 g_wt_hi[Edim * Edim];                 // out_w^T hi, [n][k]
__device__ __nv_bfloat16 g_wt_lo[Edim * Edim];                 // out_w^T lo, [n][k]

// ---------------------------------------------------------------------------
// f32x2 helpers (packed FFMA2)
// ---------------------------------------------------------------------------
__device__ __forceinline__ unsigned long long fma2(unsigned long long a,
                                                   unsigned long long b,
                                                   unsigned long long c) {
    unsigned long long d;
    asm("fma.rn.f32x2 %0, %1, %2, %3;" : "=l"(d) : "l"(a), "l"(b), "l"(c));
    return d;
}
__device__ __forceinline__ unsigned long long splat2(float v) {
    unsigned long long d;
    asm("mov.b64 %0, {%1, %1};" : "=l"(d) : "r"(__float_as_uint(v)));
    return d;
}
__device__ __forceinline__ float2 unpk2(unsigned long long v) {
    float2 r;
    asm("mov.b64 {%0, %1}, %2;" : "=f"(r.x), "=f"(r.y) : "l"(v));
    return r;
}

// ---------------------------------------------------------------------------
// Kernel 0: split out_w into transposed bf16 hi/lo:  wt[n][k] = out_w[k][n]
// ---------------------------------------------------------------------------
__global__ __launch_bounds__(256) void prep_kernel(const float* __restrict__ out_w)
{
    int idx = blockIdx.x * 256 + threadIdx.x;
    if (idx < Edim * Edim) {
        int n = idx / Edim, k = idx % Edim;
        float w = out_w[(size_t)k * Edim + n];
        __nv_bfloat16 h = __float2bfloat16(w);
        g_wt_hi[idx] = h;
        g_wt_lo[idx] = __float2bfloat16(w - __bfloat162float(h));
    }
}

// ---------------------------------------------------------------------------
// Kernel 1: pooled mean + attn GEMM (+bias,*scale) + softmax.  f32x2 over m.
// ---------------------------------------------------------------------------
__global__ __launch_bounds__(512) void attn_kernel(
    const float* __restrict__ x,
    const float* __restrict__ attn_w,
    const float* __restrict__ attn_b)
{
    __shared__ float pooled_t[64][18];          // [c][m], padded
    __shared__ float attn_s[16][NATT + 2];

    const int blk0 = blockIdx.x * 16;
    const int tid  = threadIdx.x;

    for (int idx = tid; idx < 16 * 64; idx += 512) {
        int ml = idx >> 6, c = idx & 63;
        int blk = blk0 + ml;
        int b   = blk / (HHn * WWn);
        int rem = blk % (HHn * WWn);
        int i   = rem / WWn;
        int j   = rem % WWn;
        const float* xp = x + ((size_t)((size_t)b * Hdim + 3 * i) * Wdim + 3 * j) * Cdim + c;
        float s = 0.f;
        #pragma unroll
        for (int r = 0; r < 3; r++)
            #pragma unroll
            for (int ss = 0; ss < 3; ss++)
                s += xp[((size_t)r * Wdim + ss) * Cdim];
        pooled_t[c][ml] = s * (1.f / 9.f);
    }
    __syncthreads();

    if (tid < NATT) {
        unsigned long long acc2[8];
        #pragma unroll
        for (int mp = 0; mp < 8; mp++) acc2[mp] = 0ull;
        #pragma unroll 4
        for (int c = 0; c < 64; c++) {
            unsigned long long wp = splat2(attn_w[c * NATT + tid]);
            #pragma unroll
            for (int mp = 0; mp < 8; mp++) {
                unsigned long long pp =
                    *(const unsigned long long*)&pooled_t[c][2 * mp];
                acc2[mp] = fma2(pp, wp, acc2[mp]);
            }
        }
        float bb = attn_b[tid];
        #pragma unroll
        for (int mp = 0; mp < 8; mp++) {
            float2 f = unpk2(acc2[mp]);
            attn_s[2 * mp + 0][tid] = (f.x + bb) * SCALE_F;
            attn_s[2 * mp + 1][tid] = (f.y + bb) * SCALE_F;
        }
    }
    __syncthreads();

    for (int t = tid; t < 16 * 54; t += 512) {
        int m = t / 54, g = t % 54;
        float* p = &attn_s[m][g * 9];
        float mx = p[0];
        #pragma unroll
        for (int q = 1; q < 9; q++) mx = fmaxf(mx, p[q]);
        float e[9];
        float s = 0.f;
        #pragma unroll
        for (int q = 0; q < 9; q++) { e[q] = __expf(p[q] - mx); s += e[q]; }
        float inv = 1.f / s;
        float* outp = &g_attn[(size_t)(blk0 + m) * NATT + g * 9];
        #pragma unroll
        for (int q = 0; q < 9; q++) outp[q] = e[q] * inv;
    }
}

// ---------------------------------------------------------------------------
// Kernel 2: fused v = x9@v_w and o = attn@v, f32x2 over embed-pairs.
// 4 blocks per CTA (384 threads = 12 warps, 3/SMSP) for issue density.
// ---------------------------------------------------------------------------
#define OVB 4
__global__ __launch_bounds__(96 * OVB) void ov_kernel(
    const float* __restrict__ x,
    const float* __restrict__ v_w)
{
    __shared__ float sxx[OVB][9 * 128];      // splatted x
    __shared__ float saa[OVB][NATT * 2];     // splatted attn

    const int tid  = threadIdx.x;
    const int lb   = tid / 96;
    const int ep   = tid % 96;
    const int e0   = ep * 2;
    const int blk0 = blockIdx.x * OVB;

    for (int idx = tid; idx < OVB * 144; idx += 96 * OVB) {
        int l = idx / 144, t = idx % 144;
        int blk = blk0 + l;
        int b   = blk / (HHn * WWn);
        int rem = blk % (HHn * WWn);
        int i   = rem / WWn;
        int j   = rem % WWn;
        int r = t / 48, u = t % 48;
        float4 v = *(const float4*)&x[((size_t)((size_t)b * Hdim + 3 * i + r) * Wdim + 3 * j) * Cdim + u * 4];
        int base = (r * 192 + u * 4) * 2;
        *(float2*)&sxx[l][base + 0] = make_float2(v.x, v.x);
        *(float2*)&sxx[l][base + 2] = make_float2(v.y, v.y);
        *(float2*)&sxx[l][base + 4] = make_float2(v.z, v.z);
        *(float2*)&sxx[l][base + 6] = make_float2(v.w, v.w);
    }
    for (int idx = tid; idx < OVB * NATT; idx += 96 * OVB) {
        int l = idx / NATT, t = idx % NATT;
        float a = g_attn[(size_t)(blk0 + l) * NATT + t];
        *(float2*)&saa[l][t * 2] = make_float2(a, a);
    }
    __syncthreads();

    unsigned long long vacc[9];
    #pragma unroll
    for (int p = 0; p < 9; p++) vacc[p] = 0ull;

    #pragma unroll 2
    for (int c4 = 0; c4 < 16; c4++) {
        const float* wb = &v_w[(size_t)(4 * c4) * Edim + e0];
        unsigned long long w0 = *(const unsigned long long*)(wb + 0 * Edim);
        unsigned long long w1 = *(const unsigned long long*)(wb + 1 * Edim);
        unsigned long long w2 = *(const unsigned long long*)(wb + 2 * Edim);
        unsigned long long w3 = *(const unsigned long long*)(wb + 3 * Edim);
        #pragma unroll
        for (int p = 0; p < 9; p++) {
            const unsigned long long* xp =
                (const unsigned long long*)&sxx[lb][(p * 64 + 4 * c4) * 2];
            unsigned long long a = vacc[p];
            a = fma2(xp[0], w0, a);
            a = fma2(xp[1], w1, a);
            a = fma2(xp[2], w2, a);
            a = fma2(xp[3], w3, a);
            vacc[p] = a;
        }
    }

    const int h = ep >> 4;
    const int blk = blk0 + lb;
    const int b   = blk / (HHn * WWn);
    const int rem = blk % (HHn * WWn);
    const int i   = rem / WWn;
    const int j   = rem % WWn;

    #pragma unroll
    for (int p = 0; p < 9; p++) {
        const unsigned long long* ap =
            (const unsigned long long*)&saa[lb][(h * 81 + p * 9) * 2];
        unsigned long long o2 = 0ull;
        #pragma unroll
        for (int q = 0; q < 9; q++) o2 = fma2(ap[q], vacc[q], o2);
        float2 f = unpk2(o2);

        int r = p / 3, s = p % 3;
        size_t pix = (size_t)((size_t)b * Hdim + 3 * i + r) * Wdim + 3 * j + s;
        __nv_bfloat16 hx = __float2bfloat16(f.x);
        __nv_bfloat16 hy = __float2bfloat16(f.y);
        __nv_bfloat16 lx = __float2bfloat16(f.x - __bfloat162float(hx));
        __nv_bfloat16 ly = __float2bfloat16(f.y - __bfloat162float(hy));
        *(__nv_bfloat162*)&g_mid_hi[pix * Edim + e0] = __halves2bfloat162(hx, hy);
        *(__nv_bfloat162*)&g_mid_lo[pix * Edim + e0] = __halves2bfloat162(lx, ly);
    }
}

// ---------------------------------------------------------------------------
// Kernel 3: projection via HMMA.  B (out_w^T hi/lo, all K) resident in smem;
// A chunks double-buffered via cp.async; fragments via ldmatrix.x4.
// CTA tile M=128 x N=192; 256 threads = 8 warps, warp tile 32x96.
// ---------------------------------------------------------------------------
#define BROW 400                               // padded B row (384 data + 16)
#define AROW 144                               // padded A row (128 data + 16)
#define OFF_B_HI 0
#define OFF_B_LO (192 * BROW)                  // 76800
#define OFF_A    (2 * 192 * BROW)              // 153600
#define A_BUF_SZ (2 * 128 * AROW)              // hi+lo per buffer = 36864
#define A_HL_SZ  (128 * AROW)                  // 18432
#define PSM_TOTAL (OFF_A + 2 * A_BUF_SZ)       // 227328 bytes

__device__ __forceinline__ uint32_t smem_u32(const void* p) {
    uint32_t a;
    asm("{ .reg .u64 t; cvta.to.shared.u64 t, %1; cvt.u32.u64 %0, t; }"
        : "=r"(a) : "l"(p));
    return a;
}
__device__ __forceinline__ void cpa16(uint32_t dst, const void* src) {
    asm volatile("cp.async.cg.shared.global [%0], [%1], 16;"
                 :: "r"(dst), "l"(src) : "memory");
}
__device__ __forceinline__ void ldsm_x4(uint32_t* rr, uint32_t addr) {
    asm volatile("ldmatrix.sync.aligned.m8n8.x4.shared.b16 {%0,%1,%2,%3}, [%4];"
        : "=r"(rr[0]), "=r"(rr[1]), "=r"(rr[2]), "=r"(rr[3]) : "r"(addr));
}
__device__ __forceinline__ void mma16816(float* c, const uint32_t* a,
                                         uint32_t b0, uint32_t b1) {
    asm("mma.sync.aligned.m16n8k16.row.col.f32.bf16.bf16.f32 "
        "{%0,%1,%2,%3}, {%4,%5,%6,%7}, {%8,%9}, {%0,%1,%2,%3};"
        : "+f"(c[0]), "+f"(c[1]), "+f"(c[2]), "+f"(c[3])
        : "r"(a[0]), "r"(a[1]), "r"(a[2]), "r"(a[3]), "r"(b0), "r"(b1));
}

__global__ __launch_bounds__(256) void proj_hmma_kernel(
    const float* __restrict__ out_b,
    float* __restrict__ outp)
{
    extern __shared__ char smem[];
    const uint32_t sb = smem_u32(smem);

    const int tid    = threadIdx.x;
    const int warp   = tid >> 5;
    const int lane   = tid & 31;
    const int g      = lane >> 2;
    const int t      = lane & 3;
    const int quad   = lane >> 3;
    const int r8     = lane & 7;
    const int warp_m = warp & 3;           // rows warp_m*32
    const int warp_n = warp >> 2;          // cols warp_n*96

    const size_t m0 = (size_t)blockIdx.x * 128;
    const char* Ah = (const char*)(g_mid_hi + m0 * Edim);
    const char* Al = (const char*)(g_mid_lo + m0 * Edim);

    // ---- B resident load (hi+lo), chunk A0: one cp.async group ----
    for (int idx = tid; idx < 4608; idx += 256) {
        int row = idx / 24, q = idx % 24;
        int o = row * BROW + q * 16;
        int s = row * 384 + q * 16;
        cpa16(sb + OFF_B_HI + o, (const char*)g_wt_hi + s);
        cpa16(sb + OFF_B_LO + o, (const char*)g_wt_lo + s);
    }
    #pragma unroll
    for (int it = 0; it < 4; it++) {
        int idx = it * 256 + tid;          // 0..1023
        int row = idx >> 3, q = idx & 7;
        size_t src = (size_t)row * 384 + q * 16;     // chunk 0
        uint32_t d = sb + OFF_A + row * AROW + q * 16;
        cpa16(d, Ah + src);
        cpa16(d + A_HL_SZ, Al + src);
    }
    asm volatile("cp.async.commit_group;" ::: "memory");
    asm volatile("cp.async.wait_group 0;" ::: "memory");
    __syncthreads();

    // per-lane ldmatrix address components
    const int m_off = r8 + ((quad & 1) ? 8 : 0);
    const int akoff = (quad & 2) ? 16 : 0;
    const uint32_t aAddr0 = sb + OFF_A + (warp_m * 32 + m_off) * AROW + akoff;
    const int n_off = r8 + ((quad & 2) ? 8 : 0);
    const int bkoff = (quad & 1) ? 16 : 0;
    const uint32_t bAddr0 = sb + (warp_n * 96 + n_off) * BROW + bkoff;

    float acc[2][12][4];
    #pragma unroll
    for (int mt = 0; mt < 2; mt++)
        #pragma unroll
        for (int nt = 0; nt < 12; nt++)
            #pragma unroll
            for (int q = 0; q < 4; q++) acc[mt][nt][q] = 0.f;

    for (int ch = 0; ch < 3; ch++) {
        if (ch < 2) {   // prefetch next A chunk into other buffer
            uint32_t base = sb + OFF_A + ((ch + 1) & 1) * A_BUF_SZ;
            #pragma unroll
            for (int it = 0; it < 4; it++) {
                int idx = it * 256 + tid;
                int row = idx >> 3, q = idx & 7;
                size_t src = (size_t)row * 384 + (ch + 1) * 128 + q * 16;
                uint32_t d = base + row * AROW + q * 16;
                cpa16(d, Ah + src);
                cpa16(d + A_HL_SZ, Al + src);
            }
            asm volatile("cp.async.commit_group;" ::: "memory");
        }

        const uint32_t abuf = aAddr0 + (ch & 1) * A_BUF_SZ;
        const uint32_t bko  = ch * 128;

        #pragma unroll
        for (int ks = 0; ks < 4; ks++) {
            uint32_t ah[2][4], al[2][4];
            #pragma unroll
            for (int mt = 0; mt < 2; mt++) {
                ldsm_x4(ah[mt], abuf + mt * 16 * AROW + ks * 32);
                ldsm_x4(al[mt], abuf + A_HL_SZ + mt * 16 * AROW + ks * 32);
            }
            #pragma unroll
            for (int ntp = 0; ntp < 6; ntp++) {
                uint32_t bh[4], bl[4];
                uint32_t ba = bAddr0 + ntp * 16 * BROW + bko + ks * 32;
                ldsm_x4(bh, ba + OFF_B_HI);
                ldsm_x4(bl, ba + OFF_B_LO);
                #pragma unroll
                for (int mt = 0; mt < 2; mt++) {
                    mma16816(acc[mt][2 * ntp],     ah[mt], bh[0], bh[1]);
                    mma16816(acc[mt][2 * ntp],     al[mt], bh[0], bh[1]);
                    mma16816(acc[mt][2 * ntp],     ah[mt], bl[0], bl[1]);
                    mma16816(acc[mt][2 * ntp + 1], ah[mt], bh[2], bh[3]);
                    mma16816(acc[mt][2 * ntp + 1], al[mt], bh[2], bh[3]);
                    mma16816(acc[mt][2 * ntp + 1], ah[mt], bl[2], bl[3]);
                }
            }
        }

        if (ch < 2) {
            asm volatile("cp.async.wait_group 0;" ::: "memory");
            __syncthreads();
        }
    }

    // epilogue: c0,c1 -> (row g, cols 2t,2t+1); c2,c3 -> row g+8
    #pragma unroll
    for (int nt = 0; nt < 12; nt++) {
        int col = warp_n * 96 + nt * 8 + 2 * t;
        float2 bb = *(const float2*)&out_b[col];
        #pragma unroll
        for (int mt = 0; mt < 2; mt++) {
            size_t row = m0 + warp_m * 32 + mt * 16 + g;
            float2 v0 = make_float2(acc[mt][nt][0] + bb.x, acc[mt][nt][1] + bb.y);
            float2 v1 = make_float2(acc[mt][nt][2] + bb.x, acc[mt][nt][3] + bb.y);
            *(float2*)&outp[row * Edim + col]       = v0;
            *(float2*)&outp[(row + 8) * Edim + col] = v1;
        }
    }
}

// ---------------------------------------------------------------------------
extern "C" void kernel_launch(void* const* d_in, const int* in_sizes, int n_in,
                              void* d_out, int out_size)
{
    const float* x      = (const float*)d_in[0];
    const float* v_w    = (const float*)d_in[1];
    const float* attn_w = (const float*)d_in[2];
    const float* attn_b = (const float*)d_in[3];
    const float* out_w  = (const float*)d_in[4];
    const float* out_b  = (const float*)d_in[5];
    float* outp = (float*)d_out;

    cudaFuncSetAttribute(proj_hmma_kernel,
                         cudaFuncAttributeMaxDynamicSharedMemorySize, PSM_TOTAL);

    prep_kernel<<<(Edim * Edim + 255) / 256, 256>>>(out_w);
    attn_kernel<<<NB / 16, 512>>>(x, attn_w, attn_b);
    ov_kernel<<<NB / OVB, 96 * OVB>>>(x, v_w);
    proj_hmma_kernel<<<NPIX / 128, 256, PSM_TOTAL>>>(out_b, outp);
}

// round 9
// speedup vs baseline: 1.5813x; 1.0488x over previous
#include <cuda_runtime.h>
#include <cuda_bf16.h>
#include <math.h>
#include <stdint.h>

// Problem constants
#define Bdim 8
#define Hdim 252
#define Wdim 192
#define Cdim 64
#define Edim 192
#define HHn  84
#define WWn  64
#define NB   (Bdim*HHn*WWn)        // 43008 3x3 blocks
#define NPIX (Bdim*Hdim*Wdim)      // 387072 pixels
#define NATT 486                   // K^4 * HEADS = 81*6
#define SCALE_F 0.17677669529663687f  // 32^-0.5

// Scratch (device globals; no runtime allocation allowed)
__device__ float g_attn[(size_t)NB * NATT];                    // softmaxed attention (~84 MB)
__device__ float g_v[(size_t)NPIX * Edim];                     // v = x@v_w, fp32 (~297 MB)
__device__ __nv_bfloat16 g_mid_hi[(size_t)NPIX * Edim];        // mid, bf16 hi (~149 MB)
__device__ __nv_bfloat16 g_mid_lo[(size_t)NPIX * Edim];        // mid, bf16 lo (~149 MB)
__device__ __nv_bfloat16 g_wt_hi[Edim * Edim];                 // out_w^T hi, [n][k]
__device__ __nv_bfloat16 g_wt_lo[Edim * Edim];                 // out_w^T lo, [n][k]
__device__ __nv_bfloat16 g_vt_hi[Edim * Cdim];                 // v_w^T hi, [e][c]
__device__ __nv_bfloat16 g_vt_lo[Edim * Cdim];                 // v_w^T lo, [e][c]

// ---------------------------------------------------------------------------
// helpers
// ---------------------------------------------------------------------------
__device__ __forceinline__ unsigned long long fma2(unsigned long long a,
                                                   unsigned long long b,
                                                   unsigned long long c) {
    unsigned long long d;
    asm("fma.rn.f32x2 %0, %1, %2, %3;" : "=l"(d) : "l"(a), "l"(b), "l"(c));
    return d;
}
__device__ __forceinline__ unsigned long long splat2(float v) {
    unsigned long long d;
    asm("mov.b64 %0, {%1, %1};" : "=l"(d) : "r"(__float_as_uint(v)));
    return d;
}
__device__ __forceinline__ float2 unpk2(unsigned long long v) {
    float2 r;
    asm("mov.b64 {%0, %1}, %2;" : "=f"(r.x), "=f"(r.y) : "l"(v));
    return r;
}
__device__ __forceinline__ uint32_t smem_u32(const void* p) {
    uint32_t a;
    asm("{ .reg .u64 t; cvta.to.shared.u64 t, %1; cvt.u32.u64 %0, t; }"
        : "=r"(a) : "l"(p));
    return a;
}
__device__ __forceinline__ void cpa16(uint32_t dst, const void* src) {
    asm volatile("cp.async.cg.shared.global [%0], [%1], 16;"
                 :: "r"(dst), "l"(src) : "memory");
}
__device__ __forceinline__ void ldsm_x4(uint32_t* rr, uint32_t addr) {
    asm volatile("ldmatrix.sync.aligned.m8n8.x4.shared.b16 {%0,%1,%2,%3}, [%4];"
        : "=r"(rr[0]), "=r"(rr[1]), "=r"(rr[2]), "=r"(rr[3]) : "r"(addr));
}
__device__ __forceinline__ void mma16816(float* c, const uint32_t* a,
                                         uint32_t b0, uint32_t b1) {
    asm("mma.sync.aligned.m16n8k16.row.col.f32.bf16.bf16.f32 "
        "{%0,%1,%2,%3}, {%4,%5,%6,%7}, {%8,%9}, {%0,%1,%2,%3};"
        : "+f"(c[0]), "+f"(c[1]), "+f"(c[2]), "+f"(c[3])
        : "r"(a[0]), "r"(a[1]), "r"(a[2]), "r"(a[3]), "r"(b0), "r"(b1));
}

// ---------------------------------------------------------------------------
// Kernel 0: split weights.  wt[n][k]=out_w[k][n]; vt[e][c]=v_w[c][e]
// ---------------------------------------------------------------------------
__global__ __launch_bounds__(256) void prep_kernel(const float* __restrict__ out_w,
                                                   const float* __restrict__ v_w)
{
    int idx = blockIdx.x * 256 + threadIdx.x;
    if (idx < Edim * Edim) {
        int n = idx / Edim, k = idx % Edim;
        float w = out_w[(size_t)k * Edim + n];
        __nv_bfloat16 h = __float2bfloat16(w);
        g_wt_hi[idx] = h;
        g_wt_lo[idx] = __float2bfloat16(w - __bfloat162float(h));
    }
    if (idx < Edim * Cdim) {
        int e = idx / Cdim, c = idx % Cdim;
        float w = v_w[(size_t)c * Edim + e];
        __nv_bfloat16 h = __float2bfloat16(w);
        g_vt_hi[idx] = h;
        g_vt_lo[idx] = __float2bfloat16(w - __bfloat162float(h));
    }
}

// ---------------------------------------------------------------------------
// Kernel 1: pooled mean + attn GEMM (+bias,*scale) + softmax.  f32x2 over m.
// ---------------------------------------------------------------------------
__global__ __launch_bounds__(512) void attn_kernel(
    const float* __restrict__ x,
    const float* __restrict__ attn_w,
    const float* __restrict__ attn_b)
{
    __shared__ float pooled_t[64][18];
    __shared__ float attn_s[16][NATT + 2];

    const int blk0 = blockIdx.x * 16;
    const int tid  = threadIdx.x;

    for (int idx = tid; idx < 16 * 64; idx += 512) {
        int ml = idx >> 6, c = idx & 63;
        int blk = blk0 + ml;
        int b   = blk / (HHn * WWn);
        int rem = blk % (HHn * WWn);
        int i   = rem / WWn;
        int j   = rem % WWn;
        const float* xp = x + ((size_t)((size_t)b * Hdim + 3 * i) * Wdim + 3 * j) * Cdim + c;
        float s = 0.f;
        #pragma unroll
        for (int r = 0; r < 3; r++)
            #pragma unroll
            for (int ss = 0; ss < 3; ss++)
                s += xp[((size_t)r * Wdim + ss) * Cdim];
        pooled_t[c][ml] = s * (1.f / 9.f);
    }
    __syncthreads();

    if (tid < NATT) {
        unsigned long long acc2[8];
        #pragma unroll
        for (int mp = 0; mp < 8; mp++) acc2[mp] = 0ull;
        #pragma unroll 4
        for (int c = 0; c < 64; c++) {
            unsigned long long wp = splat2(attn_w[c * NATT + tid]);
            #pragma unroll
            for (int mp = 0; mp < 8; mp++) {
                unsigned long long pp =
                    *(const unsigned long long*)&pooled_t[c][2 * mp];
                acc2[mp] = fma2(pp, wp, acc2[mp]);
            }
        }
        float bb = attn_b[tid];
        #pragma unroll
        for (int mp = 0; mp < 8; mp++) {
            float2 f = unpk2(acc2[mp]);
            attn_s[2 * mp + 0][tid] = (f.x + bb) * SCALE_F;
            attn_s[2 * mp + 1][tid] = (f.y + bb) * SCALE_F;
        }
    }
    __syncthreads();

    for (int t = tid; t < 16 * 54; t += 512) {
        int m = t / 54, g = t % 54;
        float* p = &attn_s[m][g * 9];
        float mx = p[0];
        #pragma unroll
        for (int q = 1; q < 9; q++) mx = fmaxf(mx, p[q]);
        float e[9];
        float s = 0.f;
        #pragma unroll
        for (int q = 0; q < 9; q++) { e[q] = __expf(p[q] - mx); s += e[q]; }
        float inv = 1.f / s;
        float* outp = &g_attn[(size_t)(blk0 + m) * NATT + g * 9];
        #pragma unroll
        for (int q = 0; q < 9; q++) outp[q] = e[q] * inv;
    }
}

// ---------------------------------------------------------------------------
// Kernel 2: v = x @ v_w via HMMA bf16-split (x split on the fly).
// M=128 pixels, N=192 embed, K=64.  256 threads = 8 warps (warp 32x96).
// smem 92 KB -> 2 CTAs/SM.
// ---------------------------------------------------------------------------
#define VAROW 144                              // 128B data + 16 pad
#define VOFF_A_HI 0
#define VOFF_A_LO (128 * VAROW)                // 18432
#define VOFF_B_HI (2 * 128 * VAROW)            // 36864
#define VOFF_B_LO (VOFF_B_HI + 192 * VAROW)    // 64512
#define VSM_TOTAL (VOFF_B_LO + 192 * VAROW)    // 92160

__global__ __launch_bounds__(256) void v_hmma_kernel(const float* __restrict__ x)
{
    extern __shared__ char smem[];
    const uint32_t sb = smem_u32(smem);

    const int tid    = threadIdx.x;
    const int warp   = tid >> 5;
    const int lane   = tid & 31;
    const int g      = lane >> 2;
    const int t      = lane & 3;
    const int quad   = lane >> 3;
    const int r8     = lane & 7;
    const int warp_m = warp & 3;
    const int warp_n = warp >> 2;

    const size_t m0 = (size_t)blockIdx.x * 128;

    // B: v_w^T hi/lo, 192 rows x 128B
    for (int idx = tid; idx < 1536; idx += 256) {
        int row = idx >> 3, q = idx & 7;
        int o = row * VAROW + q * 16;
        int s = row * 128 + q * 16;
        cpa16(sb + VOFF_B_HI + o, (const char*)g_vt_hi + s);
        cpa16(sb + VOFF_B_LO + o, (const char*)g_vt_lo + s);
    }
    asm volatile("cp.async.commit_group;" ::: "memory");

    // A: x tile fp32 -> bf16 hi/lo in smem.  128 rows x 64 ch.
    #pragma unroll
    for (int it = 0; it < 8; it++) {
        int idx = it * 256 + tid;              // 0..2047 float4s
        int row = idx >> 4, c4 = idx & 15;
        float4 f = *(const float4*)&x[(m0 + row) * Cdim + c4 * 4];
        __nv_bfloat16 h0 = __float2bfloat16(f.x), h1 = __float2bfloat16(f.y);
        __nv_bfloat16 h2 = __float2bfloat16(f.z), h3 = __float2bfloat16(f.w);
        __nv_bfloat162 hi01 = __halves2bfloat162(h0, h1);
        __nv_bfloat162 hi23 = __halves2bfloat162(h2, h3);
        __nv_bfloat162 lo01 = __halves2bfloat162(
            __float2bfloat16(f.x - __bfloat162float(h0)),
            __float2bfloat16(f.y - __bfloat162float(h1)));
        __nv_bfloat162 lo23 = __halves2bfloat162(
            __float2bfloat16(f.z - __bfloat162float(h2)),
            __float2bfloat16(f.w - __bfloat162float(h3)));
        int o = row * VAROW + c4 * 8;
        *(uint2*)(smem + VOFF_A_HI + o) =
            make_uint2(*(uint32_t*)&hi01, *(uint32_t*)&hi23);
        *(uint2*)(smem + VOFF_A_LO + o) =
            make_uint2(*(uint32_t*)&lo01, *(uint32_t*)&lo23);
    }
    asm volatile("cp.async.wait_group 0;" ::: "memory");
    __syncthreads();

    const int m_off = r8 + ((quad & 1) ? 8 : 0);
    const int akoff = (quad & 2) ? 16 : 0;
    const uint32_t aHi = sb + VOFF_A_HI + (warp_m * 32 + m_off) * VAROW + akoff;
    const int n_off = r8 + ((quad & 2) ? 8 : 0);
    const int bkoff = (quad & 1) ? 16 : 0;
    const uint32_t bAddr0 = sb + (warp_n * 96 + n_off) * VAROW + bkoff;

    float acc[2][12][4];
    #pragma unroll
    for (int mt = 0; mt < 2; mt++)
        #pragma unroll
        for (int nt = 0; nt < 12; nt++)
            #pragma unroll
            for (int q = 0; q < 4; q++) acc[mt][nt][q] = 0.f;

    #pragma unroll
    for (int ks = 0; ks < 4; ks++) {
        uint32_t ah[2][4], al[2][4];
        #pragma unroll
        for (int mt = 0; mt < 2; mt++) {
            ldsm_x4(ah[mt], aHi + mt * 16 * VAROW + ks * 32);
            ldsm_x4(al[mt], aHi + (VOFF_A_LO - VOFF_A_HI) + mt * 16 * VAROW + ks * 32);
        }
        #pragma unroll
        for (int ntp = 0; ntp < 6; ntp++) {
            uint32_t bh[4], bl[4];
            uint32_t ba = bAddr0 + ntp * 16 * VAROW + ks * 32;
            ldsm_x4(bh, ba + VOFF_B_HI);
            ldsm_x4(bl, ba + VOFF_B_LO);
            #pragma unroll
            for (int mt = 0; mt < 2; mt++) {
                mma16816(acc[mt][2 * ntp],     ah[mt], bh[0], bh[1]);
                mma16816(acc[mt][2 * ntp],     al[mt], bh[0], bh[1]);
                mma16816(acc[mt][2 * ntp],     ah[mt], bl[0], bl[1]);
                mma16816(acc[mt][2 * ntp + 1], ah[mt], bh[2], bh[3]);
                mma16816(acc[mt][2 * ntp + 1], al[mt], bh[2], bh[3]);
                mma16816(acc[mt][2 * ntp + 1], ah[mt], bl[2], bl[3]);
            }
        }
    }

    #pragma unroll
    for (int nt = 0; nt < 12; nt++) {
        int col = warp_n * 96 + nt * 8 + 2 * t;
        #pragma unroll
        for (int mt = 0; mt < 2; mt++) {
            size_t row = m0 + warp_m * 32 + mt * 16 + g;
            *(float2*)&g_v[row * Edim + col] =
                make_float2(acc[mt][nt][0], acc[mt][nt][1]);
            *(float2*)&g_v[(row + 8) * Edim + col] =
                make_float2(acc[mt][nt][2], acc[mt][nt][3]);
        }
    }
}

// ---------------------------------------------------------------------------
// Kernel 3: apply  o = attn @ v  per block; store mid bf16 hi/lo.
// 4 blocks per CTA, 384 threads; thread = (block, embed-pair).
// ---------------------------------------------------------------------------
#define OVB 4
__global__ __launch_bounds__(96 * OVB) void apply_kernel()
{
    __shared__ float sv[OVB][9][192];        // v, natural pair layout
    __shared__ float saa[OVB][NATT * 2];     // splatted attn

    const int tid  = threadIdx.x;
    const int lb   = tid / 96;
    const int ep   = tid % 96;
    const int e0   = ep * 2;
    const int blk0 = blockIdx.x * OVB;

    // load v rows for all 4 blocks
    for (int idx = tid; idx < OVB * 9 * 48; idx += 96 * OVB) {
        int l = idx / 432, r2 = idx % 432;
        int p = r2 / 48, u = r2 % 48;
        int blk = blk0 + l;
        int b   = blk / (HHn * WWn);
        int rem = blk % (HHn * WWn);
        int i   = rem / WWn;
        int j   = rem % WWn;
        int r = p / 3, s = p % 3;
        size_t pix = (size_t)((size_t)b * Hdim + 3 * i + r) * Wdim + 3 * j + s;
        *(float4*)&sv[l][p][u * 4] = *(const float4*)&g_v[pix * Edim + u * 4];
    }
    // load + splat attention
    for (int idx = tid; idx < OVB * NATT; idx += 96 * OVB) {
        int l = idx / NATT, t = idx % NATT;
        float a = g_attn[(size_t)(blk0 + l) * NATT + t];
        *(float2*)&saa[l][t * 2] = make_float2(a, a);
    }
    __syncthreads();

    unsigned long long vq[9];
    #pragma unroll
    for (int q = 0; q < 9; q++)
        vq[q] = *(const unsigned long long*)&sv[lb][q][e0];

    const int h = ep >> 4;
    const int blk = blk0 + lb;
    const int b   = blk / (HHn * WWn);
    const int rem = blk % (HHn * WWn);
    const int i   = rem / WWn;
    const int j   = rem % WWn;

    #pragma unroll
    for (int p = 0; p < 9; p++) {
        const unsigned long long* ap =
            (const unsigned long long*)&saa[lb][(h * 81 + p * 9) * 2];
        unsigned long long o2 = 0ull;
        #pragma unroll
        for (int q = 0; q < 9; q++) o2 = fma2(ap[q], vq[q], o2);
        float2 f = unpk2(o2);

        int r = p / 3, s = p % 3;
        size_t pix = (size_t)((size_t)b * Hdim + 3 * i + r) * Wdim + 3 * j + s;
        __nv_bfloat16 hx = __float2bfloat16(f.x);
        __nv_bfloat16 hy = __float2bfloat16(f.y);
        __nv_bfloat16 lx = __float2bfloat16(f.x - __bfloat162float(hx));
        __nv_bfloat16 ly = __float2bfloat16(f.y - __bfloat162float(hy));
        *(__nv_bfloat162*)&g_mid_hi[pix * Edim + e0] = __halves2bfloat162(hx, hy);
        *(__nv_bfloat162*)&g_mid_lo[pix * Edim + e0] = __halves2bfloat162(lx, ly);
    }
}

// ---------------------------------------------------------------------------
// Kernel 4: projection via HMMA.  B resident; A double-buffered cp.async.
// CTA tile M=128 x N=192; 512 threads = 16 warps (warp 32x48, 4/SMSP).
// ---------------------------------------------------------------------------
#define BROW 400
#define AROW 144
#define OFF_B_HI 0
#define OFF_B_LO (192 * BROW)                  // 76800
#define OFF_A    (2 * 192 * BROW)              // 153600
#define A_BUF_SZ (2 * 128 * AROW)              // 36864
#define A_HL_SZ  (128 * AROW)                  // 18432
#define PSM_TOTAL (OFF_A + 2 * A_BUF_SZ)       // 227328

__global__ __launch_bounds__(512) void proj_hmma_kernel(
    const float* __restrict__ out_b,
    float* __restrict__ outp)
{
    extern __shared__ char smem[];
    const uint32_t sb = smem_u32(smem);

    const int tid    = threadIdx.x;
    const int warp   = tid >> 5;
    const int lane   = tid & 31;
    const int g      = lane >> 2;
    const int t      = lane & 3;
    const int quad   = lane >> 3;
    const int r8     = lane & 7;
    const int warp_m = warp & 3;           // rows warp_m*32
    const int warp_n = warp >> 2;          // cols warp_n*48

    const size_t m0 = (size_t)blockIdx.x * 128;
    const char* Ah = (const char*)(g_mid_hi + m0 * Edim);
    const char* Al = (const char*)(g_mid_lo + m0 * Edim);

    // B resident (hi+lo) + A chunk 0
    for (int idx = tid; idx < 4608; idx += 512) {
        int row = idx / 24, q = idx % 24;
        int o = row * BROW + q * 16;
        int s = row * 384 + q * 16;
        cpa16(sb + OFF_B_HI + o, (const char*)g_wt_hi + s);
        cpa16(sb + OFF_B_LO + o, (const char*)g_wt_lo + s);
    }
    #pragma unroll
    for (int it = 0; it < 2; it++) {
        int idx = it * 512 + tid;          // 0..1023
        int row = idx >> 3, q = idx & 7;
        size_t src = (size_t)row * 384 + q * 16;
        uint32_t d = sb + OFF_A + row * AROW + q * 16;
        cpa16(d, Ah + src);
        cpa16(d + A_HL_SZ, Al + src);
    }
    asm volatile("cp.async.commit_group;" ::: "memory");
    asm volatile("cp.async.wait_group 0;" ::: "memory");
    __syncthreads();

    const int m_off = r8 + ((quad & 1) ? 8 : 0);
    const int akoff = (quad & 2) ? 16 : 0;
    const uint32_t aAddr0 = sb + OFF_A + (warp_m * 32 + m_off) * AROW + akoff;
    const int n_off = r8 + ((quad & 2) ? 8 : 0);
    const int bkoff = (quad & 1) ? 16 : 0;
    const uint32_t bAddr0 = sb + (warp_n * 48 + n_off) * BROW + bkoff;

    float acc[2][6][4];
    #pragma unroll
    for (int mt = 0; mt < 2; mt++)
        #pragma unroll
        for (int nt = 0; nt < 6; nt++)
            #pragma unroll
            for (int q = 0; q < 4; q++) acc[mt][nt][q] = 0.f;

    for (int ch = 0; ch < 3; ch++) {
        if (ch < 2) {
            uint32_t base = sb + OFF_A + ((ch + 1) & 1) * A_BUF_SZ;
            #pragma unroll
            for (int it = 0; it < 2; it++) {
                int idx = it * 512 + tid;
                int row = idx >> 3, q = idx & 7;
                size_t src = (size_t)row * 384 + (ch + 1) * 128 + q * 16;
                uint32_t d = base + row * AROW + q * 16;
                cpa16(d, Ah + src);
                cpa16(d + A_HL_SZ, Al + src);
            }
            asm volatile("cp.async.commit_group;" ::: "memory");
        }

        const uint32_t abuf = aAddr0 + (ch & 1) * A_BUF_SZ;
        const uint32_t bko  = ch * 128;

        #pragma unroll
        for (int ks = 0; ks < 4; ks++) {
            uint32_t ah[2][4], al[2][4];
            #pragma unroll
            for (int mt = 0; mt < 2; mt++) {
                ldsm_x4(ah[mt], abuf + mt * 16 * AROW + ks * 32);
                ldsm_x4(al[mt], abuf + A_HL_SZ + mt * 16 * AROW + ks * 32);
            }
            #pragma unroll
            for (int ntp = 0; ntp < 3; ntp++) {
                uint32_t bh[4], bl[4];
                uint32_t ba = bAddr0 + ntp * 16 * BROW + bko + ks * 32;
                ldsm_x4(bh, ba + OFF_B_HI);
                ldsm_x4(bl, ba + OFF_B_LO);
                #pragma unroll
                for (int mt = 0; mt < 2; mt++) {
                    mma16816(acc[mt][2 * ntp],     ah[mt], bh[0], bh[1]);
                    mma16816(acc[mt][2 * ntp],     al[mt], bh[0], bh[1]);
                    mma16816(acc[mt][2 * ntp],     ah[mt], bl[0], bl[1]);
                    mma16816(acc[mt][2 * ntp + 1], ah[mt], bh[2], bh[3]);
                    mma16816(acc[mt][2 * ntp + 1], al[mt], bh[2], bh[3]);
                    mma16816(acc[mt][2 * ntp + 1], ah[mt], bl[2], bl[3]);
                }
            }
        }

        if (ch < 2) {
            asm volatile("cp.async.wait_group 0;" ::: "memory");
            __syncthreads();
        }
    }

    #pragma unroll
    for (int nt = 0; nt < 6; nt++) {
        int col = warp_n * 48 + nt * 8 + 2 * t;
        float2 bb = *(const float2*)&out_b[col];
        #pragma unroll
        for (int mt = 0; mt < 2; mt++) {
            size_t row = m0 + warp_m * 32 + mt * 16 + g;
            float2 v0 = make_float2(acc[mt][nt][0] + bb.x, acc[mt][nt][1] + bb.y);
            float2 v1 = make_float2(acc[mt][nt][2] + bb.x, acc[mt][nt][3] + bb.y);
            *(float2*)&outp[row * Edim + col]       = v0;
            *(float2*)&outp[(row + 8) * Edim + col] = v1;
        }
    }
}

// ---------------------------------------------------------------------------
extern "C" void kernel_launch(void* const* d_in, const int* in_sizes, int n_in,
                              void* d_out, int out_size)
{
    const float* x      = (const float*)d_in[0];
    const float* v_w    = (const float*)d_in[1];
    const float* attn_w = (const float*)d_in[2];
    const float* attn_b = (const float*)d_in[3];
    const float* out_w  = (const float*)d_in[4];
    const float* out_b  = (const float*)d_in[5];
    float* outp = (float*)d_out;

    cudaFuncSetAttribute(v_hmma_kernel,
                         cudaFuncAttributeMaxDynamicSharedMemorySize, VSM_TOTAL);
    cudaFuncSetAttribute(proj_hmma_kernel,
                         cudaFuncAttributeMaxDynamicSharedMemorySize, PSM_TOTAL);

    prep_kernel<<<(Edim * Edim + 255) / 256, 256>>>(out_w, v_w);
    attn_kernel<<<NB / 16, 512>>>(x, attn_w, attn_b);
    v_hmma_kernel<<<NPIX / 128, 256, VSM_TOTAL>>>(x);
    apply_kernel<<<NB / OVB, 96 * OVB>>>();
    proj_hmma_kernel<<<NPIX / 128, 512, PSM_TOTAL>>>(out_b, outp);
}

// round 10
// speedup vs baseline: 1.7350x; 1.0972x over previous
#include <cuda_runtime.h>
#include <cuda_bf16.h>
#include <math.h>
#include <stdint.h>

// Problem constants
#define Bdim 8
#define Hdim 252
#define Wdim 192
#define Cdim 64
#define Edim 192
#define HHn  84
#define WWn  64
#define NB   (Bdim*HHn*WWn)        // 43008 3x3 blocks
#define NPIX (Bdim*Hdim*Wdim)      // 387072 pixels
#define NATT 486                   // K^4 * HEADS = 81*6
#define SCALE_F 0.17677669529663687f  // 32^-0.5

// Scratch (device globals; no runtime allocation allowed)
__device__ float g_attn[(size_t)NB * NATT];                    // softmaxed attention (~84 MB)
__device__ float g_v[(size_t)NPIX * Edim];                     // v = x@v_w, fp32 (~297 MB)
__device__ __nv_bfloat16 g_mid_hi[(size_t)NPIX * Edim];        // mid, bf16 hi (~149 MB)
__device__ __nv_bfloat16 g_mid_lo[(size_t)NPIX * Edim];        // mid, bf16 lo (~149 MB)
__device__ __nv_bfloat16 g_wt_hi[Edim * Edim];                 // out_w^T hi, [n][k]
__device__ __nv_bfloat16 g_wt_lo[Edim * Edim];                 // out_w^T lo, [n][k]
__device__ __nv_bfloat16 g_vt_hi[Edim * Cdim];                 // v_w^T hi, [e][c]
__device__ __nv_bfloat16 g_vt_lo[Edim * Cdim];                 // v_w^T lo, [e][c]

// ---------------------------------------------------------------------------
// helpers
// ---------------------------------------------------------------------------
__device__ __forceinline__ unsigned long long fma2(unsigned long long a,
                                                   unsigned long long b,
                                                   unsigned long long c) {
    unsigned long long d;
    asm("fma.rn.f32x2 %0, %1, %2, %3;" : "=l"(d) : "l"(a), "l"(b), "l"(c));
    return d;
}
__device__ __forceinline__ unsigned long long splat2(float v) {
    unsigned long long d;
    asm("mov.b64 %0, {%1, %1};" : "=l"(d) : "r"(__float_as_uint(v)));
    return d;
}
__device__ __forceinline__ float2 unpk2(unsigned long long v) {
    float2 r;
    asm("mov.b64 {%0, %1}, %2;" : "=f"(r.x), "=f"(r.y) : "l"(v));
    return r;
}
__device__ __forceinline__ uint32_t cvt_bf16x2(float hi, float lo) {
    uint32_t r;
    asm("cvt.rn.bf16x2.f32 %0, %1, %2;" : "=r"(r) : "f"(hi), "f"(lo));
    return r;
}
__device__ __forceinline__ uint32_t smem_u32(const void* p) {
    uint32_t a;
    asm("{ .reg .u64 t; cvta.to.shared.u64 t, %1; cvt.u32.u64 %0, t; }"
        : "=r"(a) : "l"(p));
    return a;
}
__device__ __forceinline__ void cpa16(uint32_t dst, const void* src) {
    asm volatile("cp.async.cg.shared.global [%0], [%1], 16;"
                 :: "r"(dst), "l"(src) : "memory");
}
__device__ __forceinline__ void ldsm_x4(uint32_t* rr, uint32_t addr) {
    asm volatile("ldmatrix.sync.aligned.m8n8.x4.shared.b16 {%0,%1,%2,%3}, [%4];"
        : "=r"(rr[0]), "=r"(rr[1]), "=r"(rr[2]), "=r"(rr[3]) : "r"(addr));
}
__device__ __forceinline__ void mma16816(float* c, const uint32_t* a,
                                         uint32_t b0, uint32_t b1) {
    asm("mma.sync.aligned.m16n8k16.row.col.f32.bf16.bf16.f32 "
        "{%0,%1,%2,%3}, {%4,%5,%6,%7}, {%8,%9}, {%0,%1,%2,%3};"
        : "+f"(c[0]), "+f"(c[1]), "+f"(c[2]), "+f"(c[3])
        : "r"(a[0]), "r"(a[1]), "r"(a[2]), "r"(a[3]), "r"(b0), "r"(b1));
}

// ---------------------------------------------------------------------------
// Kernel 0: split weights.  wt[n][k]=out_w[k][n]; vt[e][c]=v_w[c][e]
// ---------------------------------------------------------------------------
__global__ __launch_bounds__(256) void prep_kernel(const float* __restrict__ out_w,
                                                   const float* __restrict__ v_w)
{
    int idx = blockIdx.x * 256 + threadIdx.x;
    if (idx < Edim * Edim) {
        int n = idx / Edim, k = idx % Edim;
        float w = out_w[(size_t)k * Edim + n];
        __nv_bfloat16 h = __float2bfloat16(w);
        g_wt_hi[idx] = h;
        g_wt_lo[idx] = __float2bfloat16(w - __bfloat162float(h));
    }
    if (idx < Edim * Cdim) {
        int e = idx / Cdim, c = idx % Cdim;
        float w = v_w[(size_t)c * Edim + e];
        __nv_bfloat16 h = __float2bfloat16(w);
        g_vt_hi[idx] = h;
        g_vt_lo[idx] = __float2bfloat16(w - __bfloat162float(h));
    }
}

// ---------------------------------------------------------------------------
// Kernel 1: pooled mean + attn GEMM (+bias,*scale) + softmax.  f32x2 over m.
// ---------------------------------------------------------------------------
__global__ __launch_bounds__(512) void attn_kernel(
    const float* __restrict__ x,
    const float* __restrict__ attn_w,
    const float* __restrict__ attn_b)
{
    __shared__ float pooled_t[64][18];
    __shared__ float attn_s[16][NATT + 2];

    const int blk0 = blockIdx.x * 16;
    const int tid  = threadIdx.x;

    for (int idx = tid; idx < 16 * 64; idx += 512) {
        int ml = idx >> 6, c = idx & 63;
        int blk = blk0 + ml;
        int b   = blk / (HHn * WWn);
        int rem = blk % (HHn * WWn);
        int i   = rem / WWn;
        int j   = rem % WWn;
        const float* xp = x + ((size_t)((size_t)b * Hdim + 3 * i) * Wdim + 3 * j) * Cdim + c;
        float s = 0.f;
        #pragma unroll
        for (int r = 0; r < 3; r++)
            #pragma unroll
            for (int ss = 0; ss < 3; ss++)
                s += xp[((size_t)r * Wdim + ss) * Cdim];
        pooled_t[c][ml] = s * (1.f / 9.f);
    }
    __syncthreads();

    if (tid < NATT) {
        unsigned long long acc2[8];
        #pragma unroll
        for (int mp = 0; mp < 8; mp++) acc2[mp] = 0ull;
        #pragma unroll 4
        for (int c = 0; c < 64; c++) {
            unsigned long long wp = splat2(attn_w[c * NATT + tid]);
            #pragma unroll
            for (int mp = 0; mp < 8; mp++) {
                unsigned long long pp =
                    *(const unsigned long long*)&pooled_t[c][2 * mp];
                acc2[mp] = fma2(pp, wp, acc2[mp]);
            }
        }
        float bb = attn_b[tid];
        #pragma unroll
        for (int mp = 0; mp < 8; mp++) {
            float2 f = unpk2(acc2[mp]);
            attn_s[2 * mp + 0][tid] = (f.x + bb) * SCALE_F;
            attn_s[2 * mp + 1][tid] = (f.y + bb) * SCALE_F;
        }
    }
    __syncthreads();

    for (int t = tid; t < 16 * 54; t += 512) {
        int m = t / 54, g = t % 54;
        float* p = &attn_s[m][g * 9];
        float mx = p[0];
        #pragma unroll
        for (int q = 1; q < 9; q++) mx = fmaxf(mx, p[q]);
        float e[9];
        float s = 0.f;
        #pragma unroll
        for (int q = 0; q < 9; q++) { e[q] = __expf(p[q] - mx); s += e[q]; }
        float inv = 1.f / s;
        float* outp = &g_attn[(size_t)(blk0 + m) * NATT + g * 9];
        #pragma unroll
        for (int q = 0; q < 9; q++) outp[q] = e[q] * inv;
    }
}

// ---------------------------------------------------------------------------
// Kernel 2: v = x @ v_w via HMMA bf16-split (x split on the fly).
// M=128 pixels, N=192 embed, K=64.  256 threads = 8 warps (warp 32x96).
// ---------------------------------------------------------------------------
#define VAROW 144
#define VOFF_A_HI 0
#define VOFF_A_LO (128 * VAROW)
#define VOFF_B_HI (2 * 128 * VAROW)
#define VOFF_B_LO (VOFF_B_HI + 192 * VAROW)
#define VSM_TOTAL (VOFF_B_LO + 192 * VAROW)    // 92160

__global__ __launch_bounds__(256) void v_hmma_kernel(const float* __restrict__ x)
{
    extern __shared__ char smem[];
    const uint32_t sb = smem_u32(smem);

    const int tid    = threadIdx.x;
    const int warp   = tid >> 5;
    const int lane   = tid & 31;
    const int g      = lane >> 2;
    const int t      = lane & 3;
    const int quad   = lane >> 3;
    const int r8     = lane & 7;
    const int warp_m = warp & 3;
    const int warp_n = warp >> 2;

    const size_t m0 = (size_t)blockIdx.x * 128;

    for (int idx = tid; idx < 1536; idx += 256) {
        int row = idx >> 3, q = idx & 7;
        int o = row * VAROW + q * 16;
        int s = row * 128 + q * 16;
        cpa16(sb + VOFF_B_HI + o, (const char*)g_vt_hi + s);
        cpa16(sb + VOFF_B_LO + o, (const char*)g_vt_lo + s);
    }
    asm volatile("cp.async.commit_group;" ::: "memory");

    #pragma unroll
    for (int it = 0; it < 8; it++) {
        int idx = it * 256 + tid;
        int row = idx >> 4, c4 = idx & 15;
        float4 f = *(const float4*)&x[(m0 + row) * Cdim + c4 * 4];
        uint32_t hi01 = cvt_bf16x2(f.y, f.x);
        uint32_t hi23 = cvt_bf16x2(f.w, f.z);
        float h0 = __uint_as_float(hi01 << 16);
        float h1 = __uint_as_float(hi01 & 0xFFFF0000u);
        float h2 = __uint_as_float(hi23 << 16);
        float h3 = __uint_as_float(hi23 & 0xFFFF0000u);
        uint32_t lo01 = cvt_bf16x2(f.y - h1, f.x - h0);
        uint32_t lo23 = cvt_bf16x2(f.w - h3, f.z - h2);
        int o = row * VAROW + c4 * 8;
        *(uint2*)(smem + VOFF_A_HI + o) = make_uint2(hi01, hi23);
        *(uint2*)(smem + VOFF_A_LO + o) = make_uint2(lo01, lo23);
    }
    asm volatile("cp.async.wait_group 0;" ::: "memory");
    __syncthreads();

    const int m_off = r8 + ((quad & 1) ? 8 : 0);
    const int akoff = (quad & 2) ? 16 : 0;
    const uint32_t aHi = sb + VOFF_A_HI + (warp_m * 32 + m_off) * VAROW + akoff;
    const int n_off = r8 + ((quad & 2) ? 8 : 0);
    const int bkoff = (quad & 1) ? 16 : 0;
    const uint32_t bAddr0 = sb + (warp_n * 96 + n_off) * VAROW + bkoff;

    float acc[2][12][4];
    #pragma unroll
    for (int mt = 0; mt < 2; mt++)
        #pragma unroll
        for (int nt = 0; nt < 12; nt++)
            #pragma unroll
            for (int q = 0; q < 4; q++) acc[mt][nt][q] = 0.f;

    #pragma unroll
    for (int ks = 0; ks < 4; ks++) {
        uint32_t ah[2][4], al[2][4];
        #pragma unroll
        for (int mt = 0; mt < 2; mt++) {
            ldsm_x4(ah[mt], aHi + mt * 16 * VAROW + ks * 32);
            ldsm_x4(al[mt], aHi + (VOFF_A_LO - VOFF_A_HI) + mt * 16 * VAROW + ks * 32);
        }
        #pragma unroll
        for (int ntp = 0; ntp < 6; ntp++) {
            uint32_t bh[4], bl[4];
            uint32_t ba = bAddr0 + ntp * 16 * VAROW + ks * 32;
            ldsm_x4(bh, ba + VOFF_B_HI);
            ldsm_x4(bl, ba + VOFF_B_LO);
            #pragma unroll
            for (int mt = 0; mt < 2; mt++) {
                mma16816(acc[mt][2 * ntp],     ah[mt], bh[0], bh[1]);
                mma16816(acc[mt][2 * ntp],     al[mt], bh[0], bh[1]);
                mma16816(acc[mt][2 * ntp],     ah[mt], bl[0], bl[1]);
                mma16816(acc[mt][2 * ntp + 1], ah[mt], bh[2], bh[3]);
                mma16816(acc[mt][2 * ntp + 1], al[mt], bh[2], bh[3]);
                mma16816(acc[mt][2 * ntp + 1], ah[mt], bl[2], bl[3]);
            }
        }
    }

    #pragma unroll
    for (int nt = 0; nt < 12; nt++) {
        int col = warp_n * 96 + nt * 8 + 2 * t;
        #pragma unroll
        for (int mt = 0; mt < 2; mt++) {
            size_t row = m0 + warp_m * 32 + mt * 16 + g;
            *(float2*)&g_v[row * Edim + col] =
                make_float2(acc[mt][nt][0], acc[mt][nt][1]);
            *(float2*)&g_v[(row + 8) * Edim + col] =
                make_float2(acc[mt][nt][2], acc[mt][nt][3]);
        }
    }
}

// ---------------------------------------------------------------------------
// Kernel 3: apply  o = attn @ v ; store mid bf16 hi/lo.
// 8 blocks per CTA, 384 threads; thread = (block, 4 embeds).
// v loaded straight to registers (each element used by exactly one thread);
// attn splatted in smem; division-free loops; shift-based bf16 split.
// ---------------------------------------------------------------------------
#define OVB 8
__global__ __launch_bounds__(384) void apply_kernel()
{
    __shared__ float saa[OVB][NATT * 2];     // splatted attn

    const int tid  = threadIdx.x;
    const int lb   = tid / 48;
    const int ep   = tid % 48;
    const int e0   = ep * 4;
    const int blk0 = blockIdx.x * OVB;

    // splat attention (division-free: fixed outer trip count)
    #pragma unroll
    for (int l = 0; l < OVB; l++) {
        const float* ga = &g_attn[(size_t)(blk0 + l) * NATT];
        for (int t = tid; t < NATT; t += 384) {
            float a = ga[t];
            *(float2*)&saa[l][t * 2] = make_float2(a, a);
        }
    }

    // block decode (WWn=64 -> shifts; one const-div by 5376)
    const int blk = blk0 + lb;
    const int b   = blk / (HHn * WWn);
    const int rem = blk - b * (HHn * WWn);
    const int i   = rem >> 6;
    const int j   = rem & 63;
    const size_t pixbase = ((size_t)b * Hdim + 3 * i) * Wdim + 3 * j;

    // v rows direct to registers: 9 x LDG.128, each reused 9x
    unsigned long long vq[9][2];
    #pragma unroll
    for (int q = 0; q < 9; q++) {
        size_t pix = pixbase + (q / 3) * Wdim + (q % 3);
        ulonglong2 u = *(const ulonglong2*)&g_v[pix * Edim + e0];
        vq[q][0] = u.x;
        vq[q][1] = u.y;
    }
    __syncthreads();

    const int h = ep >> 3;                   // e0/32
    const float* ap_base = &saa[lb][h * 81 * 2];
    __nv_bfloat16* hi_base = &g_mid_hi[pixbase * Edim + e0];
    __nv_bfloat16* lo_base = &g_mid_lo[pixbase * Edim + e0];

    #pragma unroll
    for (int p = 0; p < 9; p++) {
        const unsigned long long* ap =
            (const unsigned long long*)(ap_base + p * 18);
        unsigned long long a0 = 0ull, a1 = 0ull;
        #pragma unroll
        for (int q = 0; q < 9; q++) {
            unsigned long long av = ap[q];
            a0 = fma2(av, vq[q][0], a0);
            a1 = fma2(av, vq[q][1], a1);
        }
        float2 f01 = unpk2(a0), f23 = unpk2(a1);
        uint32_t hi01 = cvt_bf16x2(f01.y, f01.x);
        uint32_t hi23 = cvt_bf16x2(f23.y, f23.x);
        float h0 = __uint_as_float(hi01 << 16);
        float h1 = __uint_as_float(hi01 & 0xFFFF0000u);
        float h2 = __uint_as_float(hi23 << 16);
        float h3 = __uint_as_float(hi23 & 0xFFFF0000u);
        uint32_t lo01 = cvt_bf16x2(f01.y - h1, f01.x - h0);
        uint32_t lo23 = cvt_bf16x2(f23.y - h3, f23.x - h2);
        const int off = ((p / 3) * Wdim + (p % 3)) * Edim;   // compile-time per p
        *(uint2*)(hi_base + off) = make_uint2(hi01, hi23);
        *(uint2*)(lo_base + off) = make_uint2(lo01, lo23);
    }
}

// ---------------------------------------------------------------------------
// Kernel 4: projection via HMMA.  B resident; A double-buffered cp.async.
// CTA tile M=128 x N=192; 512 threads = 16 warps (warp 32x48, 4/SMSP).
// ---------------------------------------------------------------------------
#define BROW 400
#define AROW 144
#define OFF_B_HI 0
#define OFF_B_LO (192 * BROW)
#define OFF_A    (2 * 192 * BROW)
#define A_BUF_SZ (2 * 128 * AROW)
#define A_HL_SZ  (128 * AROW)
#define PSM_TOTAL (OFF_A + 2 * A_BUF_SZ)       // 227328

__global__ __launch_bounds__(512) void proj_hmma_kernel(
    const float* __restrict__ out_b,
    float* __restrict__ outp)
{
    extern __shared__ char smem[];
    const uint32_t sb = smem_u32(smem);

    const int tid    = threadIdx.x;
    const int warp   = tid >> 5;
    const int lane   = tid & 31;
    const int g      = lane >> 2;
    const int t      = lane & 3;
    const int quad   = lane >> 3;
    const int r8     = lane & 7;
    const int warp_m = warp & 3;
    const int warp_n = warp >> 2;

    const size_t m0 = (size_t)blockIdx.x * 128;
    const char* Ah = (const char*)(g_mid_hi + m0 * Edim);
    const char* Al = (const char*)(g_mid_lo + m0 * Edim);

    for (int idx = tid; idx < 4608; idx += 512) {
        int row = idx / 24, q = idx % 24;
        int o = row * BROW + q * 16;
        int s = row * 384 + q * 16;
        cpa16(sb + OFF_B_HI + o, (const char*)g_wt_hi + s);
        cpa16(sb + OFF_B_LO + o, (const char*)g_wt_lo + s);
    }
    #pragma unroll
    for (int it = 0; it < 2; it++) {
        int idx = it * 512 + tid;
        int row = idx >> 3, q = idx & 7;
        size_t src = (size_t)row * 384 + q * 16;
        uint32_t d = sb + OFF_A + row * AROW + q * 16;
        cpa16(d, Ah + src);
        cpa16(d + A_HL_SZ, Al + src);
    }
    asm volatile("cp.async.commit_group;" ::: "memory");
    asm volatile("cp.async.wait_group 0;" ::: "memory");
    __syncthreads();

    const int m_off = r8 + ((quad & 1) ? 8 : 0);
    const int akoff = (quad & 2) ? 16 : 0;
    const uint32_t aAddr0 = sb + OFF_A + (warp_m * 32 + m_off) * AROW + akoff;
    const int n_off = r8 + ((quad & 2) ? 8 : 0);
    const int bkoff = (quad & 1) ? 16 : 0;
    const uint32_t bAddr0 = sb + (warp_n * 48 + n_off) * BROW + bkoff;

    float acc[2][6][4];
    #pragma unroll
    for (int mt = 0; mt < 2; mt++)
        #pragma unroll
        for (int nt = 0; nt < 6; nt++)
            #pragma unroll
            for (int q = 0; q < 4; q++) acc[mt][nt][q] = 0.f;

    for (int ch = 0; ch < 3; ch++) {
        if (ch < 2) {
            uint32_t base = sb + OFF_A + ((ch + 1) & 1) * A_BUF_SZ;
            #pragma unroll
            for (int it = 0; it < 2; it++) {
                int idx = it * 512 + tid;
                int row = idx >> 3, q = idx & 7;
                size_t src = (size_t)row * 384 + (ch + 1) * 128 + q * 16;
                uint32_t d = base + row * AROW + q * 16;
                cpa16(d, Ah + src);
                cpa16(d + A_HL_SZ, Al + src);
            }
            asm volatile("cp.async.commit_group;" ::: "memory");
        }

        const uint32_t abuf = aAddr0 + (ch & 1) * A_BUF_SZ;
        const uint32_t bko  = ch * 128;

        #pragma unroll
        for (int ks = 0; ks < 4; ks++) {
            uint32_t ah[2][4], al[2][4];
            #pragma unroll
            for (int mt = 0; mt < 2; mt++) {
                ldsm_x4(ah[mt], abuf + mt * 16 * AROW + ks * 32);
                ldsm_x4(al[mt], abuf + A_HL_SZ + mt * 16 * AROW + ks * 32);
            }
            #pragma unroll
            for (int ntp = 0; ntp < 3; ntp++) {
                uint32_t bh[4], bl[4];
                uint32_t ba = bAddr0 + ntp * 16 * BROW + bko + ks * 32;
                ldsm_x4(bh, ba + OFF_B_HI);
                ldsm_x4(bl, ba + OFF_B_LO);
                #pragma unroll
                for (int mt = 0; mt < 2; mt++) {
                    mma16816(acc[mt][2 * ntp],     ah[mt], bh[0], bh[1]);
                    mma16816(acc[mt][2 * ntp],     al[mt], bh[0], bh[1]);
                    mma16816(acc[mt][2 * ntp],     ah[mt], bl[0], bl[1]);
                    mma16816(acc[mt][2 * ntp + 1], ah[mt], bh[2], bh[3]);
                    mma16816(acc[mt][2 * ntp + 1], al[mt], bh[2], bh[3]);
                    mma16816(acc[mt][2 * ntp + 1], ah[mt], bl[2], bl[3]);
                }
            }
        }

        if (ch < 2) {
            asm volatile("cp.async.wait_group 0;" ::: "memory");
            __syncthreads();
        }
    }

    #pragma unroll
    for (int nt = 0; nt < 6; nt++) {
        int col = warp_n * 48 + nt * 8 + 2 * t;
        float2 bb = *(const float2*)&out_b[col];
        #pragma unroll
        for (int mt = 0; mt < 2; mt++) {
            size_t row = m0 + warp_m * 32 + mt * 16 + g;
            float2 v0 = make_float2(acc[mt][nt][0] + bb.x, acc[mt][nt][1] + bb.y);
            float2 v1 = make_float2(acc[mt][nt][2] + bb.x, acc[mt][nt][3] + bb.y);
            *(float2*)&outp[row * Edim + col]       = v0;
            *(float2*)&outp[(row + 8) * Edim + col] = v1;
        }
    }
}

// ---------------------------------------------------------------------------
extern "C" void kernel_launch(void* const* d_in, const int* in_sizes, int n_in,
                              void* d_out, int out_size)
{
    const float* x      = (const float*)d_in[0];
    const float* v_w    = (const float*)d_in[1];
    const float* attn_w = (const float*)d_in[2];
    const float* attn_b = (const float*)d_in[3];
    const float* out_w  = (const float*)d_in[4];
    const float* out_b  = (const float*)d_in[5];
    float* outp = (float*)d_out;

    cudaFuncSetAttribute(v_hmma_kernel,
                         cudaFuncAttributeMaxDynamicSharedMemorySize, VSM_TOTAL);
    cudaFuncSetAttribute(proj_hmma_kernel,
                         cudaFuncAttributeMaxDynamicSharedMemorySize, PSM_TOTAL);

    prep_kernel<<<(Edim * Edim + 255) / 256, 256>>>(out_w, v_w);
    attn_kernel<<<NB / 16, 512>>>(x, attn_w, attn_b);
    v_hmma_kernel<<<NPIX / 128, 256, VSM_TOTAL>>>(x);
    apply_kernel<<<NB / OVB, 384>>>();
    proj_hmma_kernel<<<NPIX / 128, 512, PSM_TOTAL>>>(out_b, outp);
}